// round 12
// baseline (speedup 1.0000x reference)
#include <cuda_runtime.h>
#include <cuda_bf16.h>
#include <math.h>
#include <stdint.h>

#define BATCH 16384
#define G 64
#define NH0 256
#define NH1 512
#define NH2 256
#define NF 4096   // G*G

// packed fp32 output: flux [B,64,64] | q [B,64] | pressure [B] | loss [1]
#define OFF_Q    ((size_t)BATCH * NF)
#define OFF_P    (OFF_Q + (size_t)BATCH * G)
#define OFF_LOSS (OFF_P + (size_t)BATCH)

// ---------------- scratch ----------------------------------------------------
__device__ float g_h0[(size_t)BATCH * NH0];
__device__ float g_t1[(size_t)BATCH * NH1];
__device__ float g_t2[(size_t)BATCH * NH2];
__device__ float g_gs[BATCH];
__device__ float g_cc[BATCH];

__device__ float* g_ptrs[3];
__global__ void k_init_ptrs() {
    g_ptrs[0] = g_h0; g_ptrs[1] = g_t1; g_ptrs[2] = g_t2;
}

// ---------------- helpers ----------------------------------------------------
__device__ __forceinline__ float geluf(float x) {
    return 0.5f * x * (1.0f + erff(x * 0.70710678118654752440f));
}

__device__ __forceinline__ float block_sum_256(float v, float* w8) {
    int lane = threadIdx.x & 31, wid = threadIdx.x >> 5;
#pragma unroll
    for (int o = 16; o > 0; o >>= 1) v += __shfl_xor_sync(0xFFFFFFFFu, v, o);
    if (lane == 0) w8[wid] = v;
    __syncthreads();
    float s = 0.0f;
#pragma unroll
    for (int i = 0; i < 8; i++) s += w8[i];
    __syncthreads();
    return s;
}

__device__ __forceinline__ uint32_t f2tf32(float f) {
    uint32_t u;
    asm("cvt.rna.tf32.f32 %0, %1;" : "=r"(u) : "f"(f));
    return u;
}

__device__ __forceinline__ uint4 cvt4(float4 v) {
    return make_uint4(f2tf32(v.x), f2tf32(v.y), f2tf32(v.z), f2tf32(v.w));
}

__device__ __forceinline__ uint32_t f2bf2(float lo, float hi) {
    __nv_bfloat162 h = __floats2bfloat162_rn(lo, hi);
    return *(uint32_t*)&h;
}

__device__ __forceinline__ void mma_tf32(float d[4],
    uint32_t a0, uint32_t a1, uint32_t a2, uint32_t a3,
    uint32_t b0, uint32_t b1)
{
    asm volatile(
        "mma.sync.aligned.m16n8k8.row.col.f32.tf32.tf32.f32 "
        "{%0,%1,%2,%3}, {%4,%5,%6,%7}, {%8,%9}, {%0,%1,%2,%3};\n"
        : "+f"(d[0]), "+f"(d[1]), "+f"(d[2]), "+f"(d[3])
        : "r"(a0), "r"(a1), "r"(a2), "r"(a3), "r"(b0), "r"(b1));
}

__device__ __forceinline__ void mma_bf16(float d[4],
    uint32_t a0, uint32_t a1, uint32_t a2, uint32_t a3,
    uint32_t b0, uint32_t b1)
{
    asm volatile(
        "mma.sync.aligned.m16n8k16.row.col.f32.bf16.bf16.f32 "
        "{%0,%1,%2,%3}, {%4,%5,%6,%7}, {%8,%9}, {%0,%1,%2,%3};\n"
        : "+f"(d[0]), "+f"(d[1]), "+f"(d[2]), "+f"(d[3])
        : "r"(a0), "r"(a1), "r"(a2), "r"(a3), "r"(b0), "r"(b1));
}

// ========== tf32 GEMM mainloop (128M x 64N, K chunk 32, single-buffered) =====
#define AS_STRIDE 36
#define BS_STRIDE 72

struct MMASmem {
    uint32_t As[128][AS_STRIDE];
    uint32_t Bs[32][BS_STRIDE];
};

template <int K, int NSTR>
__device__ __forceinline__ void mma_tiles(
    const float* __restrict__ A, const float* __restrict__ W,
    int m0, int n0, MMASmem& sm, float (&d)[2][4][4],
    int wm, int wn, int group, int tg, int tid)
{
    const float* Ag = A + (size_t)m0 * K;
    const float* Wg = W + n0;
    const int arow = tid >> 3, acol = (tid & 7) * 4;
    const int brow = tid >> 4, bcol = (tid & 15) * 4;

    float4 ra[4], rb[2];
#pragma unroll
    for (int it = 0; it < 4; it++)
        ra[it] = *(const float4*)(Ag + (size_t)(arow + 32 * it) * K + acol);
#pragma unroll
    for (int it = 0; it < 2; it++)
        rb[it] = *(const float4*)(Wg + (size_t)(brow + 16 * it) * NSTR + bcol);

#pragma unroll 1
    for (int k0 = 0; k0 < K; k0 += 32) {
#pragma unroll
        for (int it = 0; it < 4; it++)
            *(uint4*)&sm.As[arow + 32 * it][acol] = cvt4(ra[it]);
#pragma unroll
        for (int it = 0; it < 2; it++)
            *(uint4*)&sm.Bs[brow + 16 * it][bcol] = cvt4(rb[it]);
        __syncthreads();

        if (k0 + 32 < K) {
#pragma unroll
            for (int it = 0; it < 4; it++)
                ra[it] = *(const float4*)(Ag + (size_t)(arow + 32 * it) * K
                                          + (k0 + 32) + acol);
#pragma unroll
            for (int it = 0; it < 2; it++)
                rb[it] = *(const float4*)(Wg + (size_t)(k0 + 32 + brow + 16 * it) * NSTR
                                          + bcol);
        }

#pragma unroll
        for (int ks = 0; ks < 32; ks += 8) {
            uint32_t afr[2][4];
#pragma unroll
            for (int mt = 0; mt < 2; mt++) {
                int mb = wm + mt * 16;
                afr[mt][0] = sm.As[mb + group    ][ks + tg    ];
                afr[mt][1] = sm.As[mb + group + 8][ks + tg    ];
                afr[mt][2] = sm.As[mb + group    ][ks + tg + 4];
                afr[mt][3] = sm.As[mb + group + 8][ks + tg + 4];
            }
            uint32_t bfr[4][2];
#pragma unroll
            for (int nt = 0; nt < 4; nt++) {
                int nb = wn + nt * 8;
                bfr[nt][0] = sm.Bs[ks + tg    ][nb + group];
                bfr[nt][1] = sm.Bs[ks + tg + 4][nb + group];
            }
#pragma unroll
            for (int mt = 0; mt < 2; mt++)
#pragma unroll
                for (int nt = 0; nt < 4; nt++)
                    mma_tf32(d[mt][nt],
                             afr[mt][0], afr[mt][1], afr[mt][2], afr[mt][3],
                             bfr[nt][0], bfr[nt][1]);
        }
        __syncthreads();
    }
}

// ---------------- hidden GEMM: tf32 mma + bias + GELU ------------------------
template <int K, int NOUT>
__global__ __launch_bounds__(256) void k_gemm_tf32(
    int src, const float* __restrict__ W,
    const float* __restrict__ bias, int dst)
{
    const float* A = g_ptrs[src];
    float* C = g_ptrs[dst];
    __shared__ MMASmem sm;
    int tid = threadIdx.x, wid = tid >> 5, lane = tid & 31;
    int group = lane >> 2, tg = lane & 3;
    int wm = (wid >> 1) * 32, wn = (wid & 1) * 32;
    int m0 = blockIdx.y * 128, n0 = blockIdx.x * 64;
    float d[2][4][4] = {};
    mma_tiles<K, NOUT>(A, W, m0, n0, sm, d, wm, wn, group, tg, tid);
#pragma unroll
    for (int mt = 0; mt < 2; mt++) {
#pragma unroll
        for (int nt = 0; nt < 4; nt++) {
            int r0 = m0 + wm + mt * 16 + group;
            int c  = n0 + wn + nt * 8 + 2 * tg;
            float b0 = bias[c], b1 = bias[c + 1];
            float2 o0 = make_float2(geluf(d[mt][nt][0] + b0), geluf(d[mt][nt][1] + b1));
            float2 o1 = make_float2(geluf(d[mt][nt][2] + b0), geluf(d[mt][nt][3] + b1));
            *(float2*)&C[(size_t)r0 * NOUT + c]       = o0;
            *(float2*)&C[(size_t)(r0 + 8) * NOUT + c] = o1;
        }
    }
}

// ========== bf16 final GEMM: 128M x 64N, K chunk 32, 2-stage double buffer ===
#define ABF_STRIDE 20   // uint32 [m][k/2]: 16 + 4 pad
#define BBF_STRIDE 72   // uint32 [k/2][n]: 64 + 8 pad

struct MMASmemBF {
    uint32_t As[128][ABF_STRIDE];
    uint32_t Bs[16][BBF_STRIDE];
};

#define ZS_STRIDE 68    // multiple of 4: float4 epilogue loads 16B-aligned
#define NCHUNK (NH2 / 32)   // 8

__global__ __launch_bounds__(256) void k_final_mma(
    int src, const float* __restrict__ W,
    const float* __restrict__ bias, float* __restrict__ flux,
    size_t out_elems)
{
    const float* A = g_ptrs[src];
    __shared__ union {
        MMASmemBF st[2];                 // 2 x 14.5 KB
        float zs[128][ZS_STRIDE];        // 34.8 KB (union max)
    } sm;

    int tid = threadIdx.x, wid = tid >> 5, lane = tid & 31;
    int group = lane >> 2, tg = lane & 3;
    int wm = (wid >> 1) * 32, wn = (wid & 1) * 32;
    int m0 = blockIdx.y * 128;
    int n0 = blockIdx.x * 64;   // one 64-col grid row

    const float* Ag = A + (size_t)m0 * NH2;
    const float* Wg = W + n0;
    const int arow = tid >> 3, acol = (tid & 7) * 4;
    const int kb   = tid >> 4, bcol = (tid & 15) * 4;

    float d[2][4][4] = {};
    float4 ra[4], rbe, rbo;

    // load chunk 0
#pragma unroll
    for (int it = 0; it < 4; it++)
        ra[it] = *(const float4*)(Ag + (size_t)(arow + 32 * it) * NH2 + acol);
    rbe = *(const float4*)(Wg + (size_t)(2 * kb    ) * NF + bcol);
    rbo = *(const float4*)(Wg + (size_t)(2 * kb + 1) * NF + bcol);

    // commit chunk 0 to stage 0
#pragma unroll
    for (int it = 0; it < 4; it++)
        *(uint2*)&sm.st[0].As[arow + 32 * it][acol >> 1] =
            make_uint2(f2bf2(ra[it].x, ra[it].y), f2bf2(ra[it].z, ra[it].w));
    *(uint4*)&sm.st[0].Bs[kb][bcol] =
        make_uint4(f2bf2(rbe.x, rbo.x), f2bf2(rbe.y, rbo.y),
                   f2bf2(rbe.z, rbo.z), f2bf2(rbe.w, rbo.w));

    // load chunk 1
#pragma unroll
    for (int it = 0; it < 4; it++)
        ra[it] = *(const float4*)(Ag + (size_t)(arow + 32 * it) * NH2 + 32 + acol);
    rbe = *(const float4*)(Wg + (size_t)(32 + 2 * kb    ) * NF + bcol);
    rbo = *(const float4*)(Wg + (size_t)(32 + 2 * kb + 1) * NF + bcol);
    __syncthreads();

#pragma unroll 1
    for (int c = 0; c < NCHUNK; c++) {
        int cur = c & 1;
        // commit chunk c+1 (held in regs) to the other stage
        if (c + 1 < NCHUNK) {
            MMASmemBF& stg = sm.st[cur ^ 1];
#pragma unroll
            for (int it = 0; it < 4; it++)
                *(uint2*)&stg.As[arow + 32 * it][acol >> 1] =
                    make_uint2(f2bf2(ra[it].x, ra[it].y), f2bf2(ra[it].z, ra[it].w));
            *(uint4*)&stg.Bs[kb][bcol] =
                make_uint4(f2bf2(rbe.x, rbo.x), f2bf2(rbe.y, rbo.y),
                           f2bf2(rbe.z, rbo.z), f2bf2(rbe.w, rbo.w));
        }
        // prefetch chunk c+2
        if (c + 2 < NCHUNK) {
            int kg = (c + 2) * 32;
#pragma unroll
            for (int it = 0; it < 4; it++)
                ra[it] = *(const float4*)(Ag + (size_t)(arow + 32 * it) * NH2
                                          + kg + acol);
            rbe = *(const float4*)(Wg + (size_t)(kg + 2 * kb    ) * NF + bcol);
            rbo = *(const float4*)(Wg + (size_t)(kg + 2 * kb + 1) * NF + bcol);
        }
        // MMAs over current stage
        MMASmemBF& s = sm.st[cur];
#pragma unroll
        for (int ksp = 0; ksp < 16; ksp += 8) {
            uint32_t afr[2][4];
#pragma unroll
            for (int mt = 0; mt < 2; mt++) {
                int mb = wm + mt * 16;
                afr[mt][0] = s.As[mb + group    ][ksp + tg    ];
                afr[mt][1] = s.As[mb + group + 8][ksp + tg    ];
                afr[mt][2] = s.As[mb + group    ][ksp + tg + 4];
                afr[mt][3] = s.As[mb + group + 8][ksp + tg + 4];
            }
            uint32_t bfr[4][2];
#pragma unroll
            for (int nt = 0; nt < 4; nt++) {
                int nb = wn + nt * 8;
                bfr[nt][0] = s.Bs[ksp + tg    ][nb + group];
                bfr[nt][1] = s.Bs[ksp + tg + 4][nb + group];
            }
#pragma unroll
            for (int mt = 0; mt < 2; mt++)
#pragma unroll
                for (int nt = 0; nt < 4; nt++)
                    mma_bf16(d[mt][nt],
                             afr[mt][0], afr[mt][1], afr[mt][2], afr[mt][3],
                             bfr[nt][0], bfr[nt][1]);
        }
        __syncthreads();
    }

    // z (+bias) into zs (smem union reuse; all MMA reads done)
#pragma unroll
    for (int mt = 0; mt < 2; mt++) {
#pragma unroll
        for (int nt = 0; nt < 4; nt++) {
            int rb = wm + mt * 16 + group;
            int cb = wn + nt * 8 + 2 * tg;
            float bz0 = bias[n0 + cb], bz1 = bias[n0 + cb + 1];
            sm.zs[rb    ][cb    ] = d[mt][nt][0] + bz0;
            sm.zs[rb    ][cb + 1] = d[mt][nt][1] + bz1;
            sm.zs[rb + 8][cb    ] = d[mt][nt][2] + bz0;
            sm.zs[rb + 8][cb + 1] = d[mt][nt][3] + bz1;
        }
    }
    __syncthreads();

    if (tid < 128) {   // inclusive running max along the 64-col row
        float run = -3.402823466e38f;
#pragma unroll 4
        for (int j = 0; j < 64; j++) {
            run = fmaxf(run, sm.zs[tid][j]);
            sm.zs[tid][j] = run;
        }
    }
    __syncthreads();

    // flux = sigmoid(tanh(z)), float4 stores
#pragma unroll
    for (int i = 0; i < 8; i++) {
        int idx4 = tid + 256 * i;
        int r = idx4 >> 4, c = (idx4 & 15) * 4;
        float4 z = *(const float4*)&sm.zs[r][c];
        float4 f;
        float e = __expf(2.0f * z.x); float th = (e - 1.0f) / (e + 1.0f);
        f.x = 1.0f / (1.0f + __expf(-th));
        e = __expf(2.0f * z.y); th = (e - 1.0f) / (e + 1.0f);
        f.y = 1.0f / (1.0f + __expf(-th));
        e = __expf(2.0f * z.z); th = (e - 1.0f) / (e + 1.0f);
        f.z = 1.0f / (1.0f + __expf(-th));
        e = __expf(2.0f * z.w); th = (e - 1.0f) / (e + 1.0f);
        f.w = 1.0f / (1.0f + __expf(-th));
        size_t gi = (size_t)(m0 + r) * NF + n0 + c;
        if (gi + 3 < out_elems) *(float4*)&flux[gi] = f;
    }
}

// ---------------- warp-per-row LayerNorm -------------------------------------
template <int N>
__global__ __launch_bounds__(256) void k_layernorm_warp(
    int buf, const float* __restrict__ g, const float* __restrict__ be)
{
    float* data = g_ptrs[buf];
    int row  = blockIdx.x * 8 + (threadIdx.x >> 5);
    int lane = threadIdx.x & 31;
    constexpr int V = N / 128;
    float* rp = data + (size_t)row * N;
    float4 v[V];
    float s = 0.0f, s2 = 0.0f;
#pragma unroll
    for (int i = 0; i < V; i++) {
        v[i] = *(const float4*)(rp + (i * 32 + lane) * 4);
        s  += v[i].x + v[i].y + v[i].z + v[i].w;
        s2 += v[i].x * v[i].x + v[i].y * v[i].y + v[i].z * v[i].z + v[i].w * v[i].w;
    }
#pragma unroll
    for (int o = 16; o > 0; o >>= 1) {
        s  += __shfl_xor_sync(0xFFFFFFFFu, s,  o);
        s2 += __shfl_xor_sync(0xFFFFFFFFu, s2, o);
    }
    float mu  = s * (1.0f / N);
    float var = s2 * (1.0f / N) - mu * mu;
    float inv = rsqrtf(var + 1e-5f);
#pragma unroll
    for (int i = 0; i < V; i++) {
        int c = (i * 32 + lane) * 4;
        float4 gg = *(const float4*)(g + c);
        float4 bb = *(const float4*)(be + c);
        float4 o;
        o.x = (v[i].x - mu) * inv * gg.x + bb.x;
        o.y = (v[i].y - mu) * inv * gg.y + bb.y;
        o.z = (v[i].z - mu) * inv * gg.z + bb.z;
        o.w = (v[i].w - mu) * inv * gg.w + bb.w;
        *(float4*)(rp + c) = o;
    }
}

// ---------------- K1: encoder Linear(8->256) + GELU + LayerNorm --------------
__global__ __launch_bounds__(256) void k_encoder(
    const float* __restrict__ x, const float* __restrict__ W,
    const float* __restrict__ b, const float* __restrict__ g,
    const float* __restrict__ be)
{
    __shared__ float xs[8];
    __shared__ float w8[8];
    int row = blockIdx.x, t = threadIdx.x;
    if (t < 8) xs[t] = x[row * 8 + t];
    __syncthreads();
    float acc = b[t];
#pragma unroll
    for (int k = 0; k < 8; k++) acc = fmaf(xs[k], W[k * NH0 + t], acc);
    float v = geluf(acc);
    float mu  = block_sum_256(v, w8) * (1.0f / NH0);
    float d   = v - mu;
    float var = block_sum_256(d * d, w8) * (1.0f / NH0);
    g_h0[(size_t)row * NH0 + t] = d * rsqrtf(var + 1e-5f) * g[t] + be[t];
}

// ---------------- K5: per-sample physics -------------------------------------
__global__ __launch_bounds__(256) void k_physics(
    const float* __restrict__ flux, const float* __restrict__ x,
    float* __restrict__ out, size_t out_elems)
{
    __shared__ float fs[64][68];
    __shared__ float wsum[8], wq[8];
    int b = blockIdx.x, t = threadIdx.x;
    int lane = t & 31, wid = t >> 5;
    const float4* fb4 = (const float4*)(flux + (size_t)b * NF);
    float lsum = 0.0f;
#pragma unroll
    for (int i = 0; i < 4; i++) {
        int idx4 = t + 256 * i;
        float4 v = fb4[idx4];
        int r = idx4 >> 4, c = (idx4 & 15) * 4;
        *(float4*)&fs[r][c] = v;
        lsum += v.x + v.y + v.z + v.w;
    }
#pragma unroll
    for (int o = 16; o > 0; o >>= 1) lsum += __shfl_xor_sync(0xFFFFFFFFu, lsum, o);
    if (lane == 0) wsum[wid] = lsum;
    __syncthreads();

    float x0 = __ldg(x + (size_t)b * 8);
    float lq = 0.0f;
    if (t < 248) {
        int r  = (t >> 2) + 1;
        int j0 = (t & 3) * 16 + 1;
#pragma unroll
        for (int jj = 0; jj < 16; jj++) {
            int j = j0 + jj;
            if (j <= 62) {
                float lap = fs[r + 1][j] + fs[r - 1][j] + fs[r][j + 1]
                          + fs[r][j - 1] - 4.0f * fs[r][j];
                float dd = lap - x0;
                lq = fmaf(dd, dd, lq);
            }
        }
    }
#pragma unroll
    for (int o = 16; o > 0; o >>= 1) lq += __shfl_xor_sync(0xFFFFFFFFu, lq, o);
    if (lane == 0) wq[wid] = lq;
    __syncthreads();

    if (t == 0) {
        float S = 0.0f, LQ = 0.0f;
#pragma unroll
        for (int i = 0; i < 8; i++) { S += wsum[i]; LQ += wq[i]; }
        g_gs[b] = LQ + 252.0f * x0 * x0;
        float dc = x0 - S;
        g_cc[b] = dc * dc;
        size_t pi = OFF_P + (size_t)b;
        if (pi < out_elems) out[pi] = expf(-2.0f * S * (1.0f / NF));
    }
    if (t < 64) {
        size_t qi = OFF_Q + (size_t)b * G + t;
        if (qi < out_elems) out[qi] = 0.8f + (float)t * (2.7f / 63.0f);
    }
}

// ---------------- K6: scalar loss --------------------------------------------
__global__ __launch_bounds__(1024) void k_loss(const float* __restrict__ pw,
                                               float* __restrict__ out,
                                               size_t out_elems)
{
    __shared__ float r1[1024];
    __shared__ float r2[1024];
    int t = threadIdx.x;
    float sg = 0.0f, sc = 0.0f;
    for (int i = t; i < BATCH; i += 1024) { sg += g_gs[i]; sc += g_cc[i]; }
    r1[t] = sg; r2[t] = sc;
    __syncthreads();
    for (int s = 512; s > 0; s >>= 1) {
        if (t < s) { r1[t] += r1[t + s]; r2[t] += r2[t + s]; }
        __syncthreads();
    }
    if (t == 0 && OFF_LOSS < out_elems) {
        float gs_res = r1[0] * (1.0f / ((float)BATCH * (float)NF));
        float cc     = r2[0] * (1.0f / (float)BATCH);
        float stab   = fmaxf(0.0f, 1.1f - 0.8f);
        out[OFF_LOSS] = pw[0] * gs_res + pw[1] * cc + pw[2] * stab;
    }
}

// ---------------- launch -----------------------------------------------------
extern "C" void kernel_launch(void* const* d_in, const int* in_sizes, int n_in,
                              void* d_out, int out_size)
{
    (void)in_sizes; (void)n_in;
    const float* x     = (const float*)d_in[0];
    const float* Wenc  = (const float*)d_in[1];
    const float* benc  = (const float*)d_in[2];
    const float* genc  = (const float*)d_in[3];
    const float* beenc = (const float*)d_in[4];
    const float* W1    = (const float*)d_in[5];
    const float* b1    = (const float*)d_in[6];
    const float* g1    = (const float*)d_in[7];
    const float* be1   = (const float*)d_in[8];
    const float* W2    = (const float*)d_in[9];
    const float* b2    = (const float*)d_in[10];
    const float* g2    = (const float*)d_in[11];
    const float* be2   = (const float*)d_in[12];
    const float* Wf    = (const float*)d_in[13];
    const float* bf    = (const float*)d_in[14];
    const float* pw    = (const float*)d_in[15];

    float* out = (float*)d_out;
    size_t out_elems = (size_t)out_size;

    k_init_ptrs<<<1, 1>>>();
    k_encoder<<<BATCH, 256>>>(x, Wenc, benc, genc, beenc);
    k_gemm_tf32<NH0, NH1><<<dim3(NH1 / 64, BATCH / 128), 256>>>(0, W1, b1, 1);
    k_layernorm_warp<NH1><<<BATCH / 8, 256>>>(1, g1, be1);
    k_gemm_tf32<NH1, NH2><<<dim3(NH2 / 64, BATCH / 128), 256>>>(1, W2, b2, 2);
    k_layernorm_warp<NH2><<<BATCH / 8, 256>>>(2, g2, be2);
    k_final_mma<<<dim3(NF / 64, BATCH / 128), 256>>>(2, Wf, bf, out, out_elems);
    k_physics<<<BATCH, 256>>>(out, x, out, out_elems);
    k_loss<<<1, 1024>>>(pw, out, out_elems);
}

// round 13
// speedup vs baseline: 1.0002x; 1.0002x over previous
#include <cuda_runtime.h>
#include <cuda_bf16.h>
#include <math.h>
#include <stdint.h>

#define BATCH 16384
#define G 64
#define NH0 256
#define NH1 512
#define NH2 256
#define NF 4096   // G*G

// packed fp32 output: flux [B,64,64] | q [B,64] | pressure [B] | loss [1]
#define OFF_Q    ((size_t)BATCH * NF)
#define OFF_P    (OFF_Q + (size_t)BATCH * G)
#define OFF_LOSS (OFF_P + (size_t)BATCH)

// ---------------- scratch ----------------------------------------------------
__device__ float g_h0[(size_t)BATCH * NH0];
__device__ float g_t1[(size_t)BATCH * NH1];
__device__ float g_t2[(size_t)BATCH * NH2];
__device__ float g_gs[BATCH];
__device__ float g_cc[BATCH];

__device__ float* g_ptrs[3];
__global__ void k_init_ptrs() {
    g_ptrs[0] = g_h0; g_ptrs[1] = g_t1; g_ptrs[2] = g_t2;
}

// ---------------- helpers ----------------------------------------------------
__device__ __forceinline__ float geluf(float x) {
    return 0.5f * x * (1.0f + erff(x * 0.70710678118654752440f));
}

__device__ __forceinline__ float block_sum_256(float v, float* w8) {
    int lane = threadIdx.x & 31, wid = threadIdx.x >> 5;
#pragma unroll
    for (int o = 16; o > 0; o >>= 1) v += __shfl_xor_sync(0xFFFFFFFFu, v, o);
    if (lane == 0) w8[wid] = v;
    __syncthreads();
    float s = 0.0f;
#pragma unroll
    for (int i = 0; i < 8; i++) s += w8[i];
    __syncthreads();
    return s;
}

__device__ __forceinline__ uint32_t f2tf32(float f) {
    uint32_t u;
    asm("cvt.rna.tf32.f32 %0, %1;" : "=r"(u) : "f"(f));
    return u;
}

__device__ __forceinline__ uint4 cvt4(float4 v) {
    return make_uint4(f2tf32(v.x), f2tf32(v.y), f2tf32(v.z), f2tf32(v.w));
}

__device__ __forceinline__ uint32_t f2bf2(float lo, float hi) {
    __nv_bfloat162 h = __floats2bfloat162_rn(lo, hi);
    return *(uint32_t*)&h;
}

__device__ __forceinline__ void mma_tf32(float d[4],
    uint32_t a0, uint32_t a1, uint32_t a2, uint32_t a3,
    uint32_t b0, uint32_t b1)
{
    asm volatile(
        "mma.sync.aligned.m16n8k8.row.col.f32.tf32.tf32.f32 "
        "{%0,%1,%2,%3}, {%4,%5,%6,%7}, {%8,%9}, {%0,%1,%2,%3};\n"
        : "+f"(d[0]), "+f"(d[1]), "+f"(d[2]), "+f"(d[3])
        : "r"(a0), "r"(a1), "r"(a2), "r"(a3), "r"(b0), "r"(b1));
}

__device__ __forceinline__ void mma_bf16(float d[4],
    uint32_t a0, uint32_t a1, uint32_t a2, uint32_t a3,
    uint32_t b0, uint32_t b1)
{
    asm volatile(
        "mma.sync.aligned.m16n8k16.row.col.f32.bf16.bf16.f32 "
        "{%0,%1,%2,%3}, {%4,%5,%6,%7}, {%8,%9}, {%0,%1,%2,%3};\n"
        : "+f"(d[0]), "+f"(d[1]), "+f"(d[2]), "+f"(d[3])
        : "r"(a0), "r"(a1), "r"(a2), "r"(a3), "r"(b0), "r"(b1));
}

// ========== tf32 GEMM mainloop (128M x 64N, K chunk 32, single-buffered) =====
#define AS_STRIDE 36
#define BS_STRIDE 72

struct MMASmem {
    uint32_t As[128][AS_STRIDE];
    uint32_t Bs[32][BS_STRIDE];
};

template <int K, int NSTR>
__device__ __forceinline__ void mma_tiles(
    const float* __restrict__ A, const float* __restrict__ W,
    int m0, int n0, MMASmem& sm, float (&d)[2][4][4],
    int wm, int wn, int group, int tg, int tid)
{
    const float* Ag = A + (size_t)m0 * K;
    const float* Wg = W + n0;
    const int arow = tid >> 3, acol = (tid & 7) * 4;
    const int brow = tid >> 4, bcol = (tid & 15) * 4;

    float4 ra[4], rb[2];
#pragma unroll
    for (int it = 0; it < 4; it++)
        ra[it] = *(const float4*)(Ag + (size_t)(arow + 32 * it) * K + acol);
#pragma unroll
    for (int it = 0; it < 2; it++)
        rb[it] = *(const float4*)(Wg + (size_t)(brow + 16 * it) * NSTR + bcol);

#pragma unroll 1
    for (int k0 = 0; k0 < K; k0 += 32) {
#pragma unroll
        for (int it = 0; it < 4; it++)
            *(uint4*)&sm.As[arow + 32 * it][acol] = cvt4(ra[it]);
#pragma unroll
        for (int it = 0; it < 2; it++)
            *(uint4*)&sm.Bs[brow + 16 * it][bcol] = cvt4(rb[it]);
        __syncthreads();

        if (k0 + 32 < K) {
#pragma unroll
            for (int it = 0; it < 4; it++)
                ra[it] = *(const float4*)(Ag + (size_t)(arow + 32 * it) * K
                                          + (k0 + 32) + acol);
#pragma unroll
            for (int it = 0; it < 2; it++)
                rb[it] = *(const float4*)(Wg + (size_t)(k0 + 32 + brow + 16 * it) * NSTR
                                          + bcol);
        }

#pragma unroll
        for (int ks = 0; ks < 32; ks += 8) {
            uint32_t afr[2][4];
#pragma unroll
            for (int mt = 0; mt < 2; mt++) {
                int mb = wm + mt * 16;
                afr[mt][0] = sm.As[mb + group    ][ks + tg    ];
                afr[mt][1] = sm.As[mb + group + 8][ks + tg    ];
                afr[mt][2] = sm.As[mb + group    ][ks + tg + 4];
                afr[mt][3] = sm.As[mb + group + 8][ks + tg + 4];
            }
            uint32_t bfr[4][2];
#pragma unroll
            for (int nt = 0; nt < 4; nt++) {
                int nb = wn + nt * 8;
                bfr[nt][0] = sm.Bs[ks + tg    ][nb + group];
                bfr[nt][1] = sm.Bs[ks + tg + 4][nb + group];
            }
#pragma unroll
            for (int mt = 0; mt < 2; mt++)
#pragma unroll
                for (int nt = 0; nt < 4; nt++)
                    mma_tf32(d[mt][nt],
                             afr[mt][0], afr[mt][1], afr[mt][2], afr[mt][3],
                             bfr[nt][0], bfr[nt][1]);
        }
        __syncthreads();
    }
}

// ---------------- hidden GEMM: tf32 mma + bias + GELU ------------------------
template <int K, int NOUT>
__global__ __launch_bounds__(256) void k_gemm_tf32(
    int src, const float* __restrict__ W,
    const float* __restrict__ bias, int dst)
{
    const float* A = g_ptrs[src];
    float* C = g_ptrs[dst];
    __shared__ MMASmem sm;
    int tid = threadIdx.x, wid = tid >> 5, lane = tid & 31;
    int group = lane >> 2, tg = lane & 3;
    int wm = (wid >> 1) * 32, wn = (wid & 1) * 32;
    int m0 = blockIdx.y * 128, n0 = blockIdx.x * 64;
    float d[2][4][4] = {};
    mma_tiles<K, NOUT>(A, W, m0, n0, sm, d, wm, wn, group, tg, tid);
#pragma unroll
    for (int mt = 0; mt < 2; mt++) {
#pragma unroll
        for (int nt = 0; nt < 4; nt++) {
            int r0 = m0 + wm + mt * 16 + group;
            int c  = n0 + wn + nt * 8 + 2 * tg;
            float b0 = bias[c], b1 = bias[c + 1];
            float2 o0 = make_float2(geluf(d[mt][nt][0] + b0), geluf(d[mt][nt][1] + b1));
            float2 o1 = make_float2(geluf(d[mt][nt][2] + b0), geluf(d[mt][nt][3] + b1));
            *(float2*)&C[(size_t)r0 * NOUT + c]       = o0;
            *(float2*)&C[(size_t)(r0 + 8) * NOUT + c] = o1;
        }
    }
}

// ========== bf16 final GEMM: 128M x 64N, K chunk 32, 2-stage double buffer ===
#define ABF_STRIDE 20   // uint32 [m][k/2]: 16 + 4 pad
#define BBF_STRIDE 72   // uint32 [k/2][n]: 64 + 8 pad

struct MMASmemBF {
    uint32_t As[128][ABF_STRIDE];
    uint32_t Bs[16][BBF_STRIDE];
};

#define ZS_STRIDE 68    // multiple of 4: float4 epilogue loads 16B-aligned
#define NCHUNK (NH2 / 32)   // 8

__global__ __launch_bounds__(256) void k_final_mma(
    int src, const float* __restrict__ W,
    const float* __restrict__ bias, float* __restrict__ flux,
    size_t out_elems)
{
    const float* A = g_ptrs[src];
    __shared__ union {
        MMASmemBF st[2];                 // 2 x 14.5 KB
        float zs[128][ZS_STRIDE];        // 34.8 KB (union max)
    } sm;

    int tid = threadIdx.x, wid = tid >> 5, lane = tid & 31;
    int group = lane >> 2, tg = lane & 3;
    int wm = (wid >> 1) * 32, wn = (wid & 1) * 32;
    int m0 = blockIdx.y * 128;
    int n0 = blockIdx.x * 64;   // one 64-col grid row

    const float* Ag = A + (size_t)m0 * NH2;
    const float* Wg = W + n0;
    const int arow = tid >> 3, acol = (tid & 7) * 4;
    const int kb   = tid >> 4, bcol = (tid & 15) * 4;

    float d[2][4][4] = {};
    float4 ra[4], rbe, rbo;

    // load chunk 0
#pragma unroll
    for (int it = 0; it < 4; it++)
        ra[it] = *(const float4*)(Ag + (size_t)(arow + 32 * it) * NH2 + acol);
    rbe = *(const float4*)(Wg + (size_t)(2 * kb    ) * NF + bcol);
    rbo = *(const float4*)(Wg + (size_t)(2 * kb + 1) * NF + bcol);

    // commit chunk 0 to stage 0
#pragma unroll
    for (int it = 0; it < 4; it++)
        *(uint2*)&sm.st[0].As[arow + 32 * it][acol >> 1] =
            make_uint2(f2bf2(ra[it].x, ra[it].y), f2bf2(ra[it].z, ra[it].w));
    *(uint4*)&sm.st[0].Bs[kb][bcol] =
        make_uint4(f2bf2(rbe.x, rbo.x), f2bf2(rbe.y, rbo.y),
                   f2bf2(rbe.z, rbo.z), f2bf2(rbe.w, rbo.w));

    // load chunk 1
#pragma unroll
    for (int it = 0; it < 4; it++)
        ra[it] = *(const float4*)(Ag + (size_t)(arow + 32 * it) * NH2 + 32 + acol);
    rbe = *(const float4*)(Wg + (size_t)(32 + 2 * kb    ) * NF + bcol);
    rbo = *(const float4*)(Wg + (size_t)(32 + 2 * kb + 1) * NF + bcol);
    __syncthreads();

#pragma unroll 1
    for (int c = 0; c < NCHUNK; c++) {
        int cur = c & 1;
        // commit chunk c+1 (held in regs) to the other stage
        if (c + 1 < NCHUNK) {
            MMASmemBF& stg = sm.st[cur ^ 1];
#pragma unroll
            for (int it = 0; it < 4; it++)
                *(uint2*)&stg.As[arow + 32 * it][acol >> 1] =
                    make_uint2(f2bf2(ra[it].x, ra[it].y), f2bf2(ra[it].z, ra[it].w));
            *(uint4*)&stg.Bs[kb][bcol] =
                make_uint4(f2bf2(rbe.x, rbo.x), f2bf2(rbe.y, rbo.y),
                           f2bf2(rbe.z, rbo.z), f2bf2(rbe.w, rbo.w));
        }
        // prefetch chunk c+2
        if (c + 2 < NCHUNK) {
            int kg = (c + 2) * 32;
#pragma unroll
            for (int it = 0; it < 4; it++)
                ra[it] = *(const float4*)(Ag + (size_t)(arow + 32 * it) * NH2
                                          + kg + acol);
            rbe = *(const float4*)(Wg + (size_t)(kg + 2 * kb    ) * NF + bcol);
            rbo = *(const float4*)(Wg + (size_t)(kg + 2 * kb + 1) * NF + bcol);
        }
        // MMAs over current stage
        MMASmemBF& s = sm.st[cur];
#pragma unroll
        for (int ksp = 0; ksp < 16; ksp += 8) {
            uint32_t afr[2][4];
#pragma unroll
            for (int mt = 0; mt < 2; mt++) {
                int mb = wm + mt * 16;
                afr[mt][0] = s.As[mb + group    ][ksp + tg    ];
                afr[mt][1] = s.As[mb + group + 8][ksp + tg    ];
                afr[mt][2] = s.As[mb + group    ][ksp + tg + 4];
                afr[mt][3] = s.As[mb + group + 8][ksp + tg + 4];
            }
            uint32_t bfr[4][2];
#pragma unroll
            for (int nt = 0; nt < 4; nt++) {
                int nb = wn + nt * 8;
                bfr[nt][0] = s.Bs[ksp + tg    ][nb + group];
                bfr[nt][1] = s.Bs[ksp + tg + 4][nb + group];
            }
#pragma unroll
            for (int mt = 0; mt < 2; mt++)
#pragma unroll
                for (int nt = 0; nt < 4; nt++)
                    mma_bf16(d[mt][nt],
                             afr[mt][0], afr[mt][1], afr[mt][2], afr[mt][3],
                             bfr[nt][0], bfr[nt][1]);
        }
        __syncthreads();
    }

    // z (+bias) into zs (smem union reuse; all MMA reads done)
#pragma unroll
    for (int mt = 0; mt < 2; mt++) {
#pragma unroll
        for (int nt = 0; nt < 4; nt++) {
            int rb = wm + mt * 16 + group;
            int cb = wn + nt * 8 + 2 * tg;
            float bz0 = bias[n0 + cb], bz1 = bias[n0 + cb + 1];
            sm.zs[rb    ][cb    ] = d[mt][nt][0] + bz0;
            sm.zs[rb    ][cb + 1] = d[mt][nt][1] + bz1;
            sm.zs[rb + 8][cb    ] = d[mt][nt][2] + bz0;
            sm.zs[rb + 8][cb + 1] = d[mt][nt][3] + bz1;
        }
    }
    __syncthreads();

    if (tid < 128) {   // inclusive running max along the 64-col row
        float run = -3.402823466e38f;
#pragma unroll 4
        for (int j = 0; j < 64; j++) {
            run = fmaxf(run, sm.zs[tid][j]);
            sm.zs[tid][j] = run;
        }
    }
    __syncthreads();

    // flux = sigmoid(tanh(z)), float4 stores
#pragma unroll
    for (int i = 0; i < 8; i++) {
        int idx4 = tid + 256 * i;
        int r = idx4 >> 4, c = (idx4 & 15) * 4;
        float4 z = *(const float4*)&sm.zs[r][c];
        float4 f;
        float e = __expf(2.0f * z.x); float th = (e - 1.0f) / (e + 1.0f);
        f.x = 1.0f / (1.0f + __expf(-th));
        e = __expf(2.0f * z.y); th = (e - 1.0f) / (e + 1.0f);
        f.y = 1.0f / (1.0f + __expf(-th));
        e = __expf(2.0f * z.z); th = (e - 1.0f) / (e + 1.0f);
        f.z = 1.0f / (1.0f + __expf(-th));
        e = __expf(2.0f * z.w); th = (e - 1.0f) / (e + 1.0f);
        f.w = 1.0f / (1.0f + __expf(-th));
        size_t gi = (size_t)(m0 + r) * NF + n0 + c;
        if (gi + 3 < out_elems) *(float4*)&flux[gi] = f;
    }
}

// ---------------- warp-per-row LayerNorm -------------------------------------
template <int N>
__global__ __launch_bounds__(256) void k_layernorm_warp(
    int buf, const float* __restrict__ g, const float* __restrict__ be)
{
    float* data = g_ptrs[buf];
    int row  = blockIdx.x * 8 + (threadIdx.x >> 5);
    int lane = threadIdx.x & 31;
    constexpr int V = N / 128;
    float* rp = data + (size_t)row * N;
    float4 v[V];
    float s = 0.0f, s2 = 0.0f;
#pragma unroll
    for (int i = 0; i < V; i++) {
        v[i] = *(const float4*)(rp + (i * 32 + lane) * 4);
        s  += v[i].x + v[i].y + v[i].z + v[i].w;
        s2 += v[i].x * v[i].x + v[i].y * v[i].y + v[i].z * v[i].z + v[i].w * v[i].w;
    }
#pragma unroll
    for (int o = 16; o > 0; o >>= 1) {
        s  += __shfl_xor_sync(0xFFFFFFFFu, s,  o);
        s2 += __shfl_xor_sync(0xFFFFFFFFu, s2, o);
    }
    float mu  = s * (1.0f / N);
    float var = s2 * (1.0f / N) - mu * mu;
    float inv = rsqrtf(var + 1e-5f);
#pragma unroll
    for (int i = 0; i < V; i++) {
        int c = (i * 32 + lane) * 4;
        float4 gg = *(const float4*)(g + c);
        float4 bb = *(const float4*)(be + c);
        float4 o;
        o.x = (v[i].x - mu) * inv * gg.x + bb.x;
        o.y = (v[i].y - mu) * inv * gg.y + bb.y;
        o.z = (v[i].z - mu) * inv * gg.z + bb.z;
        o.w = (v[i].w - mu) * inv * gg.w + bb.w;
        *(float4*)(rp + c) = o;
    }
}

// ---------------- K1: encoder Linear(8->256) + GELU + LayerNorm --------------
__global__ __launch_bounds__(256) void k_encoder(
    const float* __restrict__ x, const float* __restrict__ W,
    const float* __restrict__ b, const float* __restrict__ g,
    const float* __restrict__ be)
{
    __shared__ float xs[8];
    __shared__ float w8[8];
    int row = blockIdx.x, t = threadIdx.x;
    if (t < 8) xs[t] = x[row * 8 + t];
    __syncthreads();
    float acc = b[t];
#pragma unroll
    for (int k = 0; k < 8; k++) acc = fmaf(xs[k], W[k * NH0 + t], acc);
    float v = geluf(acc);
    float mu  = block_sum_256(v, w8) * (1.0f / NH0);
    float d   = v - mu;
    float var = block_sum_256(d * d, w8) * (1.0f / NH0);
    g_h0[(size_t)row * NH0 + t] = d * rsqrtf(var + 1e-5f) * g[t] + be[t];
}

// ---------------- K5: per-sample physics -------------------------------------
__global__ __launch_bounds__(256) void k_physics(
    const float* __restrict__ flux, const float* __restrict__ x,
    float* __restrict__ out, size_t out_elems)
{
    __shared__ float fs[64][68];
    __shared__ float wsum[8], wq[8];
    int b = blockIdx.x, t = threadIdx.x;
    int lane = t & 31, wid = t >> 5;
    const float4* fb4 = (const float4*)(flux + (size_t)b * NF);
    float lsum = 0.0f;
#pragma unroll
    for (int i = 0; i < 4; i++) {
        int idx4 = t + 256 * i;
        float4 v = fb4[idx4];
        int r = idx4 >> 4, c = (idx4 & 15) * 4;
        *(float4*)&fs[r][c] = v;
        lsum += v.x + v.y + v.z + v.w;
    }
#pragma unroll
    for (int o = 16; o > 0; o >>= 1) lsum += __shfl_xor_sync(0xFFFFFFFFu, lsum, o);
    if (lane == 0) wsum[wid] = lsum;
    __syncthreads();

    float x0 = __ldg(x + (size_t)b * 8);
    float lq = 0.0f;
    if (t < 248) {
        int r  = (t >> 2) + 1;
        int j0 = (t & 3) * 16 + 1;
#pragma unroll
        for (int jj = 0; jj < 16; jj++) {
            int j = j0 + jj;
            if (j <= 62) {
                float lap = fs[r + 1][j] + fs[r - 1][j] + fs[r][j + 1]
                          + fs[r][j - 1] - 4.0f * fs[r][j];
                float dd = lap - x0;
                lq = fmaf(dd, dd, lq);
            }
        }
    }
#pragma unroll
    for (int o = 16; o > 0; o >>= 1) lq += __shfl_xor_sync(0xFFFFFFFFu, lq, o);
    if (lane == 0) wq[wid] = lq;
    __syncthreads();

    if (t == 0) {
        float S = 0.0f, LQ = 0.0f;
#pragma unroll
        for (int i = 0; i < 8; i++) { S += wsum[i]; LQ += wq[i]; }
        g_gs[b] = LQ + 252.0f * x0 * x0;
        float dc = x0 - S;
        g_cc[b] = dc * dc;
        size_t pi = OFF_P + (size_t)b;
        if (pi < out_elems) out[pi] = expf(-2.0f * S * (1.0f / NF));
    }
    if (t < 64) {
        size_t qi = OFF_Q + (size_t)b * G + t;
        if (qi < out_elems) out[qi] = 0.8f + (float)t * (2.7f / 63.0f);
    }
}

// ---------------- K6: scalar loss --------------------------------------------
__global__ __launch_bounds__(1024) void k_loss(const float* __restrict__ pw,
                                               float* __restrict__ out,
                                               size_t out_elems)
{
    __shared__ float r1[1024];
    __shared__ float r2[1024];
    int t = threadIdx.x;
    float sg = 0.0f, sc = 0.0f;
    for (int i = t; i < BATCH; i += 1024) { sg += g_gs[i]; sc += g_cc[i]; }
    r1[t] = sg; r2[t] = sc;
    __syncthreads();
    for (int s = 512; s > 0; s >>= 1) {
        if (t < s) { r1[t] += r1[t + s]; r2[t] += r2[t + s]; }
        __syncthreads();
    }
    if (t == 0 && OFF_LOSS < out_elems) {
        float gs_res = r1[0] * (1.0f / ((float)BATCH * (float)NF));
        float cc     = r2[0] * (1.0f / (float)BATCH);
        float stab   = fmaxf(0.0f, 1.1f - 0.8f);
        out[OFF_LOSS] = pw[0] * gs_res + pw[1] * cc + pw[2] * stab;
    }
}

// ---------------- launch -----------------------------------------------------
extern "C" void kernel_launch(void* const* d_in, const int* in_sizes, int n_in,
                              void* d_out, int out_size)
{
    (void)in_sizes; (void)n_in;
    const float* x     = (const float*)d_in[0];
    const float* Wenc  = (const float*)d_in[1];
    const float* benc  = (const float*)d_in[2];
    const float* genc  = (const float*)d_in[3];
    const float* beenc = (const float*)d_in[4];
    const float* W1    = (const float*)d_in[5];
    const float* b1    = (const float*)d_in[6];
    const float* g1    = (const float*)d_in[7];
    const float* be1   = (const float*)d_in[8];
    const float* W2    = (const float*)d_in[9];
    const float* b2    = (const float*)d_in[10];
    const float* g2    = (const float*)d_in[11];
    const float* be2   = (const float*)d_in[12];
    const float* Wf    = (const float*)d_in[13];
    const float* bf    = (const float*)d_in[14];
    const float* pw    = (const float*)d_in[15];

    float* out = (float*)d_out;
    size_t out_elems = (size_t)out_size;

    k_init_ptrs<<<1, 1>>>();
    k_encoder<<<BATCH, 256>>>(x, Wenc, benc, genc, beenc);
    k_gemm_tf32<NH0, NH1><<<dim3(NH1 / 64, BATCH / 128), 256>>>(0, W1, b1, 1);
    k_layernorm_warp<NH1><<<BATCH / 8, 256>>>(1, g1, be1);
    k_gemm_tf32<NH1, NH2><<<dim3(NH2 / 64, BATCH / 128), 256>>>(1, W2, b2, 2);
    k_layernorm_warp<NH2><<<BATCH / 8, 256>>>(2, g2, be2);
    k_final_mma<<<dim3(NF / 64, BATCH / 128), 256>>>(2, Wf, bf, out, out_elems);
    k_physics<<<BATCH, 256>>>(out, x, out, out_elems);
    k_loss<<<1, 1024>>>(pw, out, out_elems);
}